// round 3
// baseline (speedup 1.0000x reference)
#include <cuda_runtime.h>
#include <math.h>

#define C_CH  4096
#define IMGSZ 64
#define NPM   4
#define OUT_N (C_CH * IMGSZ * IMGSZ)   // 16777216 elements per multiplier index

// Scratch (no allocations allowed): effective weights + running max (as monotone uint keys)
__device__ float        g_w[NPM * 9];
__device__ unsigned int g_maxbits[NPM];

// Monotone float<->uint key mapping so atomicMax(uint) == float max
__device__ __forceinline__ unsigned fkey(float f) {
    unsigned b = __float_as_uint(f);
    return (b & 0x80000000u) ? ~b : (b | 0x80000000u);
}
__device__ __forceinline__ float keyf(unsigned k) {
    return __uint_as_float((k & 0x80000000u) ? (k ^ 0x80000000u) : ~k);
}

// ---------------------------------------------------------------------------
// Kernel 0: build effective 3x3 kernels, reset max accumulators
// w_eff[n][k] = clip(weight[n][k], -1, 1) * clip(weight_factor[n], 1, 255)
// ---------------------------------------------------------------------------
__global__ void prep_kernel(const float* __restrict__ w, const float* __restrict__ wf) {
    int t = threadIdx.x;
    if (t < NPM * 9) {
        int n = t / 9;
        float wv = fminf(fmaxf(w[t], -1.f), 1.f);
        float f  = fminf(fmaxf(wf[n], 1.f), 255.f);
        g_w[t] = wv * f;
    }
    if (t < NPM) g_maxbits[t] = 0u;   // key(0)=0 < key(any real float)
}

// Load one image row segment: cols [w0-1 .. w0+4] with zero padding.
__device__ __forceinline__ void load_row(const float* __restrict__ img, int r, int w0,
                                         bool hl, bool hr, float v[6]) {
    if ((unsigned)r < (unsigned)IMGSZ) {
        const float4 m = *reinterpret_cast<const float4*>(img + (r << 6) + w0);
        v[0] = hl ? img[(r << 6) + w0 - 1] : 0.f;
        v[1] = m.x; v[2] = m.y; v[3] = m.z; v[4] = m.w;
        v[5] = hr ? img[(r << 6) + w0 + 4] : 0.f;
    } else {
        v[0] = v[1] = v[2] = v[3] = v[4] = v[5] = 0.f;
    }
}

// ---------------------------------------------------------------------------
// Kernel A: conv (4 kernels x all channels) + global max per multiplier index
// One block per channel. 256 threads, each owns a 4-wide x 4-tall tile.
// ---------------------------------------------------------------------------
__global__ void __launch_bounds__(256)
conv_max_kernel(const float* __restrict__ in) {
    int c = blockIdx.x;
    const float* img = in + c * (IMGSZ * IMGSZ);
    int tid = threadIdx.x;
    int tx = tid & 15, ty = tid >> 4;
    int w0 = tx << 2, r0 = ty << 2;
    bool hl = (tx != 0), hr = (tx != 15);

    float wv[36];
#pragma unroll
    for (int k = 0; k < 36; k++) wv[k] = g_w[k];

    float rows[3][6];
    load_row(img, r0 - 1, w0, hl, hr, rows[0]);
    load_row(img, r0,     w0, hl, hr, rows[1]);

    const float NEG_INF = __int_as_float(0xff800000);
    float mx[4] = {NEG_INF, NEG_INF, NEG_INF, NEG_INF};

#pragma unroll
    for (int orr = 0; orr < 4; orr++) {
        load_row(img, r0 + orr + 1, w0, hl, hr, rows[2]);
#pragma unroll
        for (int n = 0; n < 4; n++) {
            const float* wn = wv + n * 9;
#pragma unroll
            for (int oc = 0; oc < 4; oc++) {
                float a =        wn[0] * rows[0][oc];
                a = fmaf(wn[1], rows[0][oc + 1], a);
                a = fmaf(wn[2], rows[0][oc + 2], a);
                a = fmaf(wn[3], rows[1][oc],     a);
                a = fmaf(wn[4], rows[1][oc + 1], a);
                a = fmaf(wn[5], rows[1][oc + 2], a);
                a = fmaf(wn[6], rows[2][oc],     a);
                a = fmaf(wn[7], rows[2][oc + 1], a);
                a = fmaf(wn[8], rows[2][oc + 2], a);
                mx[n] = fmaxf(mx[n], a);
            }
        }
#pragma unroll
        for (int j = 0; j < 6; j++) { rows[0][j] = rows[1][j]; rows[1][j] = rows[2][j]; }
    }

    // warp-level max reduce
#pragma unroll
    for (int n = 0; n < 4; n++) {
#pragma unroll
        for (int off = 16; off; off >>= 1)
            mx[n] = fmaxf(mx[n], __shfl_xor_sync(0xffffffffu, mx[n], off));
    }

    __shared__ float red[8][4];
    int wid = tid >> 5, lane = tid & 31;
    if (lane == 0) {
        red[wid][0] = mx[0]; red[wid][1] = mx[1];
        red[wid][2] = mx[2]; red[wid][3] = mx[3];
    }
    __syncthreads();
    if (tid < 4) {
        float m = red[0][tid];
#pragma unroll
        for (int wi = 1; wi < 8; wi++) m = fmaxf(m, red[wi][tid]);
        atomicMax(&g_maxbits[tid], fkey(m));
    }
}

// ---------------------------------------------------------------------------
// Kernel C: recompute conv, apply power-of-two renorm, add input, store.
// out[n,0,c,h,w] = input[c,h,w] + conv_n(c,h,w) * scale_n
// scale_n = (max_n/128 > 0) ? 2^-round(log2(max_n/128)) : 1
// ---------------------------------------------------------------------------
__global__ void __launch_bounds__(256)
conv_out_kernel(const float* __restrict__ in, float* __restrict__ out) {
    int c = blockIdx.x;
    const float* img = in + c * (IMGSZ * IMGSZ);
    int tid = threadIdx.x;
    int tx = tid & 15, ty = tid >> 4;
    int w0 = tx << 2, r0 = ty << 2;
    bool hl = (tx != 0), hr = (tx != 15);

    float wv[36];
#pragma unroll
    for (int k = 0; k < 36; k++) wv[k] = g_w[k];

    float sc[4];
#pragma unroll
    for (int n = 0; n < 4; n++) {
        float m   = keyf(g_maxbits[n]);
        float div = m * 0.0078125f;   // /128
        float s = 1.f;
        if (div > 0.f) s = exp2f(-rintf(log2f(div)));   // rintf = round-half-even, matches jnp.round
        sc[n] = s;
    }

    float rows[3][6];
    load_row(img, r0 - 1, w0, hl, hr, rows[0]);
    load_row(img, r0,     w0, hl, hr, rows[1]);

    float* outc = out + c * (IMGSZ * IMGSZ) + w0;

#pragma unroll
    for (int orr = 0; orr < 4; orr++) {
        load_row(img, r0 + orr + 1, w0, hl, hr, rows[2]);
        int rowoff = (r0 + orr) << 6;
#pragma unroll
        for (int n = 0; n < 4; n++) {
            const float* wn = wv + n * 9;
            float4 o;
#pragma unroll
            for (int oc = 0; oc < 4; oc++) {
                float a =        wn[0] * rows[0][oc];
                a = fmaf(wn[1], rows[0][oc + 1], a);
                a = fmaf(wn[2], rows[0][oc + 2], a);
                a = fmaf(wn[3], rows[1][oc],     a);
                a = fmaf(wn[4], rows[1][oc + 1], a);
                a = fmaf(wn[5], rows[1][oc + 2], a);
                a = fmaf(wn[6], rows[2][oc],     a);
                a = fmaf(wn[7], rows[2][oc + 1], a);
                a = fmaf(wn[8], rows[2][oc + 2], a);
                float r = fmaf(a, sc[n], rows[1][oc + 1]);  // input + scaled conv
                ((float*)&o)[oc] = r;
            }
            *reinterpret_cast<float4*>(outc + n * OUT_N + rowoff) = o;
        }
#pragma unroll
        for (int j = 0; j < 6; j++) { rows[0][j] = rows[1][j]; rows[1][j] = rows[2][j]; }
    }
}

// ---------------------------------------------------------------------------
extern "C" void kernel_launch(void* const* d_in, const int* in_sizes, int n_in,
                              void* d_out, int out_size) {
    const float* input  = (const float*)d_in[0];   // [1,4096,64,64]
    const float* weight = (const float*)d_in[1];   // [4,9]
    const float* wf     = (const float*)d_in[2];   // [4,1]
    float* out = (float*)d_out;                    // [4,1,4096,64,64]

    prep_kernel<<<1, 64>>>(weight, wf);
    conv_max_kernel<<<C_CH, 256>>>(input);
    conv_out_kernel<<<C_CH, 256>>>(input, out);
}

// round 5
// speedup vs baseline: 1.0490x; 1.0490x over previous
#include <cuda_runtime.h>
#include <math.h>

#define C_CH  4096
#define IMGSZ 64
#define NPM   4
#define OUT_N (C_CH * IMGSZ * IMGSZ)   // elements per multiplier index

typedef unsigned long long u64;

// Scratch: effective weights + running max (monotone uint keys)
__device__ float        g_w[NPM * 9];
__device__ unsigned int g_maxbits[NPM];

__device__ __forceinline__ unsigned fkey(float f) {
    unsigned b = __float_as_uint(f);
    return (b & 0x80000000u) ? ~b : (b | 0x80000000u);
}
__device__ __forceinline__ float keyf(unsigned k) {
    return __uint_as_float((k & 0x80000000u) ? (k ^ 0x80000000u) : ~k);
}

// ---- packed f32x2 helpers (sm_103a FFMA2 path; ptxas won't auto-fuse) ----
__device__ __forceinline__ u64 pack2(float lo, float hi) {
    u64 r;
    asm("mov.b64 %0, {%1, %2};" : "=l"(r) : "r"(__float_as_uint(lo)), "r"(__float_as_uint(hi)));
    return r;
}
__device__ __forceinline__ u64 dup2(float v) { return pack2(v, v); }
__device__ __forceinline__ void unpack2(u64 p, float& lo, float& hi) {
    unsigned a, b;
    asm("mov.b64 {%0, %1}, %2;" : "=r"(a), "=r"(b) : "l"(p));
    lo = __uint_as_float(a); hi = __uint_as_float(b);
}
__device__ __forceinline__ u64 mul2(u64 a, u64 b) {
    u64 r; asm("mul.rn.f32x2 %0, %1, %2;" : "=l"(r) : "l"(a), "l"(b)); return r;
}
__device__ __forceinline__ u64 fma2(u64 a, u64 b, u64 c) {
    u64 r; asm("fma.rn.f32x2 %0, %1, %2, %3;" : "=l"(r) : "l"(a), "l"(b), "l"(c)); return r;
}

// ---------------------------------------------------------------------------
// Kernel 0: build effective 3x3 kernels, reset max accumulators
// ---------------------------------------------------------------------------
__global__ void prep_kernel(const float* __restrict__ w, const float* __restrict__ wf) {
    int t = threadIdx.x;
    if (t < NPM * 9) {
        int n = t / 9;
        float wv = fminf(fmaxf(w[t], -1.f), 1.f);
        float f  = fminf(fmaxf(wf[n], 1.f), 255.f);
        g_w[t] = wv * f;
    }
    if (t < NPM) g_maxbits[t] = 0u;
}

// Load one image row segment cols [w0-1 .. w0+4] (zero-padded), duplicated
// into f32x2 broadcast pairs.
__device__ __forceinline__ void load_row_dup(const float* __restrict__ img, int r, int w0,
                                             bool hl, bool hr, u64 d[6]) {
    if ((unsigned)r < (unsigned)IMGSZ) {
        const float4 m = *reinterpret_cast<const float4*>(img + (r << 6) + w0);
        d[0] = dup2(hl ? img[(r << 6) + w0 - 1] : 0.f);
        d[1] = dup2(m.x); d[2] = dup2(m.y); d[3] = dup2(m.z); d[4] = dup2(m.w);
        d[5] = dup2(hr ? img[(r << 6) + w0 + 4] : 0.f);
    } else {
#pragma unroll
        for (int j = 0; j < 6; j++) d[j] = 0ull;
    }
}

// 9-tap packed conv for one output pixel, multiplier-pair p.
// Tap order identical to the scalar version -> bit-exact results.
__device__ __forceinline__ u64 conv9(const u64* wp, const u64 r0[6], const u64 r1[6],
                                     const u64 r2[6], int oc) {
    u64 a = mul2(wp[0], r0[oc]);
    a = fma2(wp[1], r0[oc + 1], a);
    a = fma2(wp[2], r0[oc + 2], a);
    a = fma2(wp[3], r1[oc],     a);
    a = fma2(wp[4], r1[oc + 1], a);
    a = fma2(wp[5], r1[oc + 2], a);
    a = fma2(wp[6], r2[oc],     a);
    a = fma2(wp[7], r2[oc + 1], a);
    a = fma2(wp[8], r2[oc + 2], a);
    return a;
}

// ---------------------------------------------------------------------------
// Kernel A: conv (4 kernels x all channels) + global max per multiplier index
// One block per channel, 256 threads, 4x4 px per thread. n packed pairwise
// into f32x2 lanes: (n0,n1) and (n2,n3).
// ---------------------------------------------------------------------------
__global__ void __launch_bounds__(256)
conv_max_kernel(const float* __restrict__ in) {
    int c = blockIdx.x;
    const float* img = in + c * (IMGSZ * IMGSZ);
    int tid = threadIdx.x;
    int tx = tid & 15, ty = tid >> 4;
    int w0 = tx << 2, r0 = ty << 2;
    bool hl = (tx != 0), hr = (tx != 15);

    u64 wp[2][9];
#pragma unroll
    for (int p = 0; p < 2; p++)
#pragma unroll
        for (int j = 0; j < 9; j++)
            wp[p][j] = pack2(g_w[(2 * p) * 9 + j], g_w[(2 * p + 1) * 9 + j]);

    u64 rw[3][6];
    load_row_dup(img, r0 - 1, w0, hl, hr, rw[0]);
    load_row_dup(img, r0,     w0, hl, hr, rw[1]);

    const float NEG_INF = __int_as_float(0xff800000);
    float mx[4] = {NEG_INF, NEG_INF, NEG_INF, NEG_INF};

#pragma unroll
    for (int orr = 0; orr < 4; orr++) {
        load_row_dup(img, r0 + orr + 1, w0, hl, hr, rw[2]);
#pragma unroll
        for (int p = 0; p < 2; p++) {
#pragma unroll
            for (int oc = 0; oc < 4; oc++) {
                u64 a = conv9(wp[p], rw[0], rw[1], rw[2], oc);
                float f0, f1; unpack2(a, f0, f1);
                mx[2 * p]     = fmaxf(mx[2 * p],     f0);
                mx[2 * p + 1] = fmaxf(mx[2 * p + 1], f1);
            }
        }
#pragma unroll
        for (int j = 0; j < 6; j++) { rw[0][j] = rw[1][j]; rw[1][j] = rw[2][j]; }
    }

#pragma unroll
    for (int n = 0; n < 4; n++) {
#pragma unroll
        for (int off = 16; off; off >>= 1)
            mx[n] = fmaxf(mx[n], __shfl_xor_sync(0xffffffffu, mx[n], off));
    }

    __shared__ float red[8][4];
    int wid = tid >> 5, lane = tid & 31;
    if (lane == 0) {
        red[wid][0] = mx[0]; red[wid][1] = mx[1];
        red[wid][2] = mx[2]; red[wid][3] = mx[3];
    }
    __syncthreads();
    if (tid < 4) {
        float m = red[0][tid];
#pragma unroll
        for (int wi = 1; wi < 8; wi++) m = fmaxf(m, red[wi][tid]);
        atomicMax(&g_maxbits[tid], fkey(m));
    }
}

// ---------------------------------------------------------------------------
// Kernel C: recompute conv, power-of-two renorm, add input, store.
// ---------------------------------------------------------------------------
__global__ void __launch_bounds__(256)
conv_out_kernel(const float* __restrict__ in, float* __restrict__ out) {
    int c = blockIdx.x;
    const float* img = in + c * (IMGSZ * IMGSZ);
    int tid = threadIdx.x;
    int tx = tid & 15, ty = tid >> 4;
    int w0 = tx << 2, r0 = ty << 2;
    bool hl = (tx != 0), hr = (tx != 15);

    u64 wp[2][9];
#pragma unroll
    for (int p = 0; p < 2; p++)
#pragma unroll
        for (int j = 0; j < 9; j++)
            wp[p][j] = pack2(g_w[(2 * p) * 9 + j], g_w[(2 * p + 1) * 9 + j]);

    u64 scp[2];
    {
        float sc[4];
#pragma unroll
        for (int n = 0; n < 4; n++) {
            float m   = keyf(g_maxbits[n]);
            float div = m * 0.0078125f;   // /128
            float s = 1.f;
            if (div > 0.f) s = exp2f(-rintf(log2f(div)));
            sc[n] = s;
        }
        scp[0] = pack2(sc[0], sc[1]);
        scp[1] = pack2(sc[2], sc[3]);
    }

    u64 rw[3][6];
    load_row_dup(img, r0 - 1, w0, hl, hr, rw[0]);
    load_row_dup(img, r0,     w0, hl, hr, rw[1]);

    float* outc = out + c * (IMGSZ * IMGSZ) + w0;

#pragma unroll
    for (int orr = 0; orr < 4; orr++) {
        load_row_dup(img, r0 + orr + 1, w0, hl, hr, rw[2]);
        int rowoff = (r0 + orr) << 6;
        float4 o0, o1, o2, o3;   // per-n output rows
        float* op[4] = {(float*)&o0, (float*)&o1, (float*)&o2, (float*)&o3};
#pragma unroll
        for (int p = 0; p < 2; p++) {
#pragma unroll
            for (int oc = 0; oc < 4; oc++) {
                u64 a = conv9(wp[p], rw[0], rw[1], rw[2], oc);
                // r = input_center + a * scale  (packed fma; input broadcast pair)
                u64 r = fma2(a, scp[p], rw[1][oc + 1]);
                float f0, f1; unpack2(r, f0, f1);
                op[2 * p][oc]     = f0;
                op[2 * p + 1][oc] = f1;
            }
        }
        *reinterpret_cast<float4*>(outc + 0 * OUT_N + rowoff) = o0;
        *reinterpret_cast<float4*>(outc + 1 * OUT_N + rowoff) = o1;
        *reinterpret_cast<float4*>(outc + 2 * OUT_N + rowoff) = o2;
        *reinterpret_cast<float4*>(outc + 3 * OUT_N + rowoff) = o3;
#pragma unroll
        for (int j = 0; j < 6; j++) { rw[0][j] = rw[1][j]; rw[1][j] = rw[2][j]; }
    }
}

// ---------------------------------------------------------------------------
extern "C" void kernel_launch(void* const* d_in, const int* in_sizes, int n_in,
                              void* d_out, int out_size) {
    const float* input  = (const float*)d_in[0];   // [1,4096,64,64]
    const float* weight = (const float*)d_in[1];   // [4,9]
    const float* wf     = (const float*)d_in[2];   // [4,1]
    float* out = (float*)d_out;                    // [4,1,4096,64,64]

    prep_kernel<<<1, 64>>>(weight, wf);
    conv_max_kernel<<<C_CH, 256>>>(input);
    conv_out_kernel<<<C_CH, 256>>>(input, out);
}